// round 14
// baseline (speedup 1.0000x reference)
#include <cuda_runtime.h>

// Problem constants
#define BB 8
#define HH 256
#define WW 256
#define HWSZ (HH*WW)
#define PP 7
#define HALF 3
#define NUM_PATCHES 32
#define BN_EPS 1e-5f

// ---------------- scratch (device globals; no allocations) ----------------
__device__ float g_y1[BB * 32  * HWSZ];   //  64 MB
__device__ float g_y2[BB * 64  * HWSZ];   // 128 MB
__device__ float g_y3[BB * 128 * HWSZ];   // 256 MB
__device__ float g_scale1[32],  g_shift1[32];
__device__ float g_scale2[64],  g_shift2[64];
__device__ float g_scale3[128], g_shift3[128];

// ---------------- conv 3x3 SAME, fused input-affine+lrelu ----------------
// LAYER selects buffers: 1: img -> g_y1 ; 2: g_y1 -> g_y2 (affine1) ; 3: g_y2 -> g_y3 (affine2)
template<int LAYER, int IC, int OC>
__global__ __launch_bounds__(256, 1)
void conv3x3_kernel(const float* __restrict__ img,
                    const float* __restrict__ wgt,   // (OC, IC, 3, 3)
                    const float* __restrict__ bias)  // (OC)
{
    constexpr int OCC = 8;   // output channels per block
    constexpr int TW  = 32;  // tile width
    constexpr int TH  = 64;  // tile height (8 rows per thread)
    constexpr bool AFFINE = (LAYER != 1);

    const float* in  = (LAYER == 1) ? img  : (LAYER == 2 ? g_y1 : g_y2);
    float*       out = (LAYER == 1) ? g_y1 : (LAYER == 2 ? g_y2 : g_y3);
    const float* scl = (LAYER == 2) ? g_scale1 : g_scale2;
    const float* shf = (LAYER == 2) ? g_shift1 : g_shift2;

    __shared__ float s_in[(TH + 2) * (TW + 2)];
    __shared__ float s_w[OCC * IC * 9];

    const int tid = threadIdx.x;
    const int tx  = tid & 31;
    const int ty  = tid >> 5;           // 0..7
    const int x0  = blockIdx.x * TW;
    const int y0  = blockIdx.y * TH;
    const int bz  = blockIdx.z;
    const int b   = bz / (OC / OCC);
    const int oc0 = (bz % (OC / OCC)) * OCC;

    // preload this block's weight chunk: [OCC][IC][9]
    for (int i = tid; i < OCC * IC * 9; i += 256) {
        int ocl = i / (IC * 9);
        int rem = i - ocl * (IC * 9);
        s_w[i] = wgt[(oc0 + ocl) * IC * 9 + rem];
    }

    float acc[8][OCC];
    #pragma unroll
    for (int p = 0; p < 8; p++)
        #pragma unroll
        for (int o = 0; o < OCC; o++) acc[p][o] = 0.f;

    const float* inb = in + (size_t)b * IC * HWSZ;

    for (int ic = 0; ic < IC; ic++) {
        __syncthreads();
        float sc = 1.f, sh = 0.f;
        if (AFFINE) { sc = scl[ic]; sh = shf[ic]; }
        const float* inc = inb + (size_t)ic * HWSZ;
        // load (TH+2)x(TW+2) halo tile; zero-pad out of bounds (SAME conv pads
        // the *post-BN-lrelu* input with zeros, so pad AFTER affine == 0).
        for (int i = tid; i < (TH + 2) * (TW + 2); i += 256) {
            int r  = i / (TW + 2);
            int c  = i - r * (TW + 2);
            int gy = y0 - 1 + r;
            int gx = x0 - 1 + c;
            float v = 0.f;
            if ((unsigned)gy < HH && (unsigned)gx < WW) {
                v = inc[gy * WW + gx];
                if (AFFINE) {
                    v = fmaf(sc, v, sh);
                    v = v > 0.f ? v : 0.01f * v;
                }
            }
            s_in[i] = v;
        }
        __syncthreads();

        // gather 10 rows x 3 cols of input once (reused across 8 oc)
        float vin[10][3];
        #pragma unroll
        for (int r = 0; r < 10; r++)
            #pragma unroll
            for (int c = 0; c < 3; c++)
                vin[r][c] = s_in[(ty * 8 + r) * (TW + 2) + tx + c];

        #pragma unroll
        for (int o = 0; o < OCC; o++) {
            float wv[9];
            #pragma unroll
            for (int k = 0; k < 9; k++) wv[k] = s_w[(o * IC + ic) * 9 + k];
            #pragma unroll
            for (int p = 0; p < 8; p++) {
                float s;
                s  = vin[p    ][0] * wv[0];
                s  = fmaf(vin[p    ][1], wv[1], s);
                s  = fmaf(vin[p    ][2], wv[2], s);
                s  = fmaf(vin[p + 1][0], wv[3], s);
                s  = fmaf(vin[p + 1][1], wv[4], s);
                s  = fmaf(vin[p + 1][2], wv[5], s);
                s  = fmaf(vin[p + 2][0], wv[6], s);
                s  = fmaf(vin[p + 2][1], wv[7], s);
                s  = fmaf(vin[p + 2][2], wv[8], s);
                acc[p][o] += s;
            }
        }
    }

    // write y = conv + bias
    #pragma unroll
    for (int o = 0; o < OCC; o++) {
        float bv = bias[oc0 + o];
        float* op = out + (size_t)(b * OC + oc0 + o) * HWSZ;
        #pragma unroll
        for (int p = 0; p < 8; p++) {
            int gy = y0 + ty * 8 + p;
            op[gy * WW + x0 + tx] = acc[p][o] + bv;
        }
    }
}

// ---------------- per-channel BN stats -> folded scale/shift ----------------
template<int LAYER, int C>
__global__ __launch_bounds__(512)
void bn_stats_kernel(const float* __restrict__ gamma,
                     const float* __restrict__ beta)
{
    const float* y     = (LAYER == 1) ? g_y1 : (LAYER == 2 ? g_y2 : g_y3);
    float*       scale = (LAYER == 1) ? g_scale1 : (LAYER == 2 ? g_scale2 : g_scale3);
    float*       shift = (LAYER == 1) ? g_shift1 : (LAYER == 2 ? g_shift2 : g_shift3);

    const int c = blockIdx.x;
    float s = 0.f, s2 = 0.f;
    for (int b = 0; b < BB; b++) {
        const float4* p = (const float4*)(y + (size_t)(b * C + c) * HWSZ);
        for (int i = threadIdx.x; i < HWSZ / 4; i += 512) {
            float4 v = p[i];
            s  += v.x + v.y + v.z + v.w;
            s2  = fmaf(v.x, v.x, s2);
            s2  = fmaf(v.y, v.y, s2);
            s2  = fmaf(v.z, v.z, s2);
            s2  = fmaf(v.w, v.w, s2);
        }
    }
    __shared__ float rs[512], rs2[512];
    rs[threadIdx.x] = s;
    rs2[threadIdx.x] = s2;
    __syncthreads();
    for (int off = 256; off > 0; off >>= 1) {
        if (threadIdx.x < off) {
            rs[threadIdx.x]  += rs[threadIdx.x + off];
            rs2[threadIdx.x] += rs2[threadIdx.x + off];
        }
        __syncthreads();
    }
    if (threadIdx.x == 0) {
        const float n    = (float)(BB * HWSZ);
        float mean = rs[0] / n;
        float var  = rs2[0] / n - mean * mean;
        float sc   = gamma[c] * rsqrtf(var + BN_EPS);
        scale[c]   = sc;
        shift[c]   = beta[c] - mean * sc;
    }
}

// ---------------- patches (from raw image) + encoded gather ----------------
__global__ void finalize_kernel(const float* __restrict__ image,
                                const int* __restrict__ a_xy,
                                const int* __restrict__ p_xy,
                                const int* __restrict__ n_xy,
                                float* __restrict__ out)
{
    const int b   = blockIdx.x;
    const int tid = threadIdx.x;
    const int* xys[3] = { a_xy, p_xy, n_xy };

    #pragma unroll
    for (int s = 0; s < 3; s++) {
        int x0 = xys[s][(b * NUM_PATCHES + NUM_PATCHES - 1) * 2 + 0] - HALF;
        int y0 = xys[s][(b * NUM_PATCHES + NUM_PATCHES - 1) * 2 + 1] - HALF;
        x0 = max(0, min(x0, HH - PP));
        y0 = max(0, min(y0, WW - PP));
        for (int i = tid; i < 3 * PP * PP; i += blockDim.x) {
            int c = i / (PP * PP);
            int r = (i / PP) % PP;
            int q = i % PP;
            out[s * BB * 3 * PP * PP + b * 3 * PP * PP + i] =
                image[(size_t)(b * 3 + c) * HWSZ + (x0 + r) * WW + (y0 + q)];
        }
    }

    // encoded_anchor_patches uses n_xy (matches reference) + BN3 + lrelu
    int nx = n_xy[(b * NUM_PATCHES + NUM_PATCHES - 1) * 2 + 0];
    int ny = n_xy[(b * NUM_PATCHES + NUM_PATCHES - 1) * 2 + 1];
    for (int c = tid; c < 128; c += blockDim.x) {
        float v = g_y3[(size_t)(b * 128 + c) * HWSZ + nx * WW + ny];
        v = fmaf(g_scale3[c], v, g_shift3[c]);
        v = v > 0.f ? v : 0.01f * v;
        out[3 * BB * 3 * PP * PP + b * 128 + c] = v;
    }
}

// ---------------- launch ----------------
extern "C" void kernel_launch(void* const* d_in, const int* in_sizes, int n_in,
                              void* d_out, int out_size)
{
    (void)in_sizes; (void)n_in; (void)out_size;
    const float* image = (const float*)d_in[0];
    const int*   a_xy  = (const int*)d_in[1];
    const int*   p_xy  = (const int*)d_in[2];
    const int*   n_xy  = (const int*)d_in[3];
    const float* w1    = (const float*)d_in[4];
    const float* b1    = (const float*)d_in[5];
    const float* g1    = (const float*)d_in[6];
    const float* bt1   = (const float*)d_in[7];
    const float* w2    = (const float*)d_in[8];
    const float* b2    = (const float*)d_in[9];
    const float* g2    = (const float*)d_in[10];
    const float* bt2   = (const float*)d_in[11];
    const float* w3    = (const float*)d_in[12];
    const float* b3    = (const float*)d_in[13];
    const float* g3    = (const float*)d_in[14];
    const float* bt3   = (const float*)d_in[15];
    // d_in[16] recon_w, d_in[17] recon_b: computed but not returned by reference
    float* out = (float*)d_out;

    dim3 blk(256);
    // layer 1: 3 -> 32
    conv3x3_kernel<1, 3, 32><<<dim3(WW/32, HH/64, BB * (32/8)), blk>>>(image, w1, b1);
    bn_stats_kernel<1, 32><<<32, 512>>>(g1, bt1);
    // layer 2: 32 -> 64 (BN1+lrelu fused into input load)
    conv3x3_kernel<2, 32, 64><<<dim3(WW/32, HH/64, BB * (64/8)), blk>>>(image, w2, b2);
    bn_stats_kernel<2, 64><<<64, 512>>>(g2, bt2);
    // layer 3: 64 -> 128 (BN2+lrelu fused)
    conv3x3_kernel<3, 64, 128><<<dim3(WW/32, HH/64, BB * (128/8)), blk>>>(image, w3, b3);
    bn_stats_kernel<3, 128><<<128, 512>>>(g3, bt3);
    // outputs
    finalize_kernel<<<BB, 256>>>(image, a_xy, p_xy, n_xy, out);
}

// round 15
// speedup vs baseline: 1.2001x; 1.2001x over previous
#include <cuda_runtime.h>

// Problem constants
#define BB 8
#define HH 256
#define WW 256
#define HWSZ (HH*WW)
#define PP 7
#define HALF 3
#define NUM_PATCHES 32
#define BN_EPS 1e-5f

// ---------------- scratch (device globals; no allocations) ----------------
__device__ float g_y1[BB * 32  * HWSZ];   //  64 MB
__device__ float g_y2[BB * 64  * HWSZ];   // 128 MB
__device__ float g_y3[BB * 128 * HWSZ];   // 256 MB
__device__ float g_scale1[32],  g_shift1[32];
__device__ float g_scale2[64],  g_shift2[64];
__device__ float g_scale3[128], g_shift3[128];
__device__ float g_part[2][128 * BB];     // per-(channel,batch) partial sums

// ---------------- packed f32x2 helpers (sm_100+ PTX) ----------------
__device__ __forceinline__ unsigned long long pk2(float lo, float hi) {
    unsigned long long r;
    asm("mov.b64 %0, {%1, %2};" : "=l"(r) : "f"(lo), "f"(hi));
    return r;
}
__device__ __forceinline__ void upk2(unsigned long long v, float& lo, float& hi) {
    asm("mov.b64 {%0, %1}, %2;" : "=f"(lo), "=f"(hi) : "l"(v));
}
__device__ __forceinline__ void ffma2(unsigned long long& c,
                                      unsigned long long a,
                                      unsigned long long b) {
    asm("fma.rn.f32x2 %0, %1, %2, %3;" : "=l"(c) : "l"(a), "l"(b), "l"(c));
}

// ---------------- conv 3x3 SAME, fused input-affine+lrelu, FFMA2 ----------
// LAYER 1: img -> g_y1 ; 2: g_y1 -> g_y2 (affine1+lrelu) ; 3: g_y2 -> g_y3 (affine2+lrelu)
template<int LAYER, int IC, int OC>
__global__ __launch_bounds__(256)
void conv3x3_kernel(const float* __restrict__ img,
                    const float* __restrict__ wgt,   // (OC, IC, 3, 3)
                    const float* __restrict__ bias)  // (OC)
{
    constexpr int OCC  = 8;                 // output channels per block
    constexpr int TW   = 32;                // tile width
    constexpr int TH   = 64;                // tile height (8 rows per thread)
    constexpr int TILE = (TH + 2) * (TW + 2);   // 2244
    constexpr int NL   = (TILE + 255) / 256;    // 9 loads per thread
    constexpr bool AFFINE = (LAYER != 1);

    const float* in  = (LAYER == 1) ? img  : (LAYER == 2 ? g_y1 : g_y2);
    float*       out = (LAYER == 1) ? g_y1 : (LAYER == 2 ? g_y2 : g_y3);
    const float* scl = (LAYER == 2) ? g_scale1 : g_scale2;
    const float* shf = (LAYER == 2) ? g_shift1 : g_shift2;

    __shared__ float  s_in[TILE];
    __shared__ float2 s_w2[OCC * IC * 9];   // duplicated weights for LDS.64 broadcast

    const int tid = threadIdx.x;
    const int tx  = tid & 31;
    const int ty  = tid >> 5;               // 0..7
    const int x0  = blockIdx.x * TW;
    const int y0  = blockIdx.y * TH;
    const int bz  = blockIdx.z;
    const int b   = bz / (OC / OCC);
    const int oc0 = (bz % (OC / OCC)) * OCC;

    // preload + duplicate this block's weight chunk: [OCC][IC][9] as (w,w)
    for (int i = tid; i < OCC * IC * 9; i += 256) {
        int ocl = i / (IC * 9);
        int rem = i - ocl * (IC * 9);
        float w = wgt[(oc0 + ocl) * IC * 9 + rem];
        s_w2[i] = make_float2(w, w);
    }

    unsigned long long acc[4][OCC];         // row-pairs (2pp, 2pp+1) x OCC
    #pragma unroll
    for (int pp = 0; pp < 4; pp++)
        #pragma unroll
        for (int o = 0; o < OCC; o++) acc[pp][o] = 0ULL;

    const float* inb = in + (size_t)b * IC * HWSZ;

    // register prefetch buffer for the next ic's tile
    float pf[NL];
    {
        const float* inc = inb;             // ic = 0
        #pragma unroll
        for (int j = 0; j < NL; j++) {
            int i = j * 256 + tid;
            float v = 0.f;
            if (i < TILE) {
                int r = i / (TW + 2), c = i - r * (TW + 2);
                int gy = y0 - 1 + r, gx = x0 - 1 + c;
                if ((unsigned)gy < HH && (unsigned)gx < WW) v = inc[gy * WW + gx];
            }
            pf[j] = v;
        }
    }

    for (int ic = 0; ic < IC; ic++) {
        float sc = 1.f, sh = 0.f;
        if (AFFINE) { sc = scl[ic]; sh = shf[ic]; }

        __syncthreads();   // previous compute done reading s_in
        // stage prefetched values -> smem (affine+lrelu applied; OOB stays 0 = SAME pad)
        #pragma unroll
        for (int j = 0; j < NL; j++) {
            int i = j * 256 + tid;
            if (i < TILE) {
                int r = i / (TW + 2), c = i - r * (TW + 2);
                int gy = y0 - 1 + r, gx = x0 - 1 + c;
                float v = 0.f;
                if ((unsigned)gy < HH && (unsigned)gx < WW) {
                    v = pf[j];
                    if (AFFINE) {
                        v = fmaf(sc, v, sh);
                        v = v > 0.f ? v : 0.01f * v;
                    }
                }
                s_in[i] = v;
            }
        }
        __syncthreads();

        // issue next ic's global loads now; latency hides under compute below
        if (ic + 1 < IC) {
            const float* inc = inb + (size_t)(ic + 1) * HWSZ;
            #pragma unroll
            for (int j = 0; j < NL; j++) {
                int i = j * 256 + tid;
                float v = 0.f;
                if (i < TILE) {
                    int r = i / (TW + 2), c = i - r * (TW + 2);
                    int gy = y0 - 1 + r, gx = x0 - 1 + c;
                    if ((unsigned)gy < HH && (unsigned)gx < WW) v = inc[gy * WW + gx];
                }
                pf[j] = v;
            }
        }

        // pack vertical row-pairs: vp[r][c] = (vin[r], vin[r+1]) for output-row pairs
        unsigned long long vp[9][3];
        #pragma unroll
        for (int c = 0; c < 3; c++) {
            float prev = s_in[(ty * 8) * (TW + 2) + tx + c];
            #pragma unroll
            for (int r = 0; r < 9; r++) {
                float nxt = s_in[(ty * 8 + r + 1) * (TW + 2) + tx + c];
                vp[r][c] = pk2(prev, nxt);
                prev = nxt;
            }
        }

        #pragma unroll
        for (int o = 0; o < OCC; o++) {
            const float2* wp = &s_w2[(o * IC + ic) * 9];
            unsigned long long w[9];
            #pragma unroll
            for (int k = 0; k < 9; k++)
                w[k] = *reinterpret_cast<const unsigned long long*>(&wp[k]);
            #pragma unroll
            for (int pp = 0; pp < 4; pp++) {
                #pragma unroll
                for (int kr = 0; kr < 3; kr++) {
                    #pragma unroll
                    for (int kc = 0; kc < 3; kc++)
                        ffma2(acc[pp][o], vp[2 * pp + kr][kc], w[kr * 3 + kc]);
                }
            }
        }
    }

    // write y = conv + bias
    #pragma unroll
    for (int o = 0; o < OCC; o++) {
        float bv = bias[oc0 + o];
        float* op = out + (size_t)(b * OC + oc0 + o) * HWSZ;
        #pragma unroll
        for (int pp = 0; pp < 4; pp++) {
            float lo, hi;
            upk2(acc[pp][o], lo, hi);
            int gy = y0 + ty * 8 + 2 * pp;
            op[gy * WW + x0 + tx]       = lo + bv;
            op[(gy + 1) * WW + x0 + tx] = hi + bv;
        }
    }
}

// ---------------- BN stats: stage 1, per-(channel,batch) partials ----------
template<int LAYER, int C>
__global__ __launch_bounds__(256)
void bn_partial_kernel()
{
    const float* y = (LAYER == 1) ? g_y1 : (LAYER == 2 ? g_y2 : g_y3);
    const int c = blockIdx.x / BB;
    const int b = blockIdx.x % BB;
    const float4* p = (const float4*)(y + (size_t)(b * C + c) * HWSZ);

    float s = 0.f, s2 = 0.f;
    for (int i = threadIdx.x; i < HWSZ / 4; i += 256) {
        float4 v = p[i];
        s += v.x + v.y + v.z + v.w;
        s2 = fmaf(v.x, v.x, s2);
        s2 = fmaf(v.y, v.y, s2);
        s2 = fmaf(v.z, v.z, s2);
        s2 = fmaf(v.w, v.w, s2);
    }
    __shared__ float rs[256], rs2[256];
    rs[threadIdx.x] = s; rs2[threadIdx.x] = s2;
    __syncthreads();
    for (int off = 128; off > 0; off >>= 1) {
        if (threadIdx.x < off) {
            rs[threadIdx.x]  += rs[threadIdx.x + off];
            rs2[threadIdx.x] += rs2[threadIdx.x + off];
        }
        __syncthreads();
    }
    if (threadIdx.x == 0) {
        g_part[0][blockIdx.x] = rs[0];
        g_part[1][blockIdx.x] = rs2[0];
    }
}

// ---------------- BN stats: stage 2, fold into scale/shift ----------------
template<int LAYER, int C>
__global__ void bn_final_kernel(const float* __restrict__ gamma,
                                const float* __restrict__ beta)
{
    float* scale = (LAYER == 1) ? g_scale1 : (LAYER == 2 ? g_scale2 : g_scale3);
    float* shift = (LAYER == 1) ? g_shift1 : (LAYER == 2 ? g_shift2 : g_shift3);
    int c = blockIdx.x * blockDim.x + threadIdx.x;
    if (c >= C) return;
    float s = 0.f, s2 = 0.f;
    #pragma unroll
    for (int b = 0; b < BB; b++) {
        s  += g_part[0][c * BB + b];
        s2 += g_part[1][c * BB + b];
    }
    const float n = (float)(BB * HWSZ);
    float mean = s / n;
    float var  = s2 / n - mean * mean;
    float sc   = gamma[c] * rsqrtf(var + BN_EPS);
    scale[c]   = sc;
    shift[c]   = beta[c] - mean * sc;
}

// ---------------- patches (from raw image) + encoded gather ----------------
__global__ void finalize_kernel(const float* __restrict__ image,
                                const int* __restrict__ a_xy,
                                const int* __restrict__ p_xy,
                                const int* __restrict__ n_xy,
                                float* __restrict__ out)
{
    const int b   = blockIdx.x;
    const int tid = threadIdx.x;
    const int* xys[3] = { a_xy, p_xy, n_xy };

    #pragma unroll
    for (int s = 0; s < 3; s++) {
        int x0 = xys[s][(b * NUM_PATCHES + NUM_PATCHES - 1) * 2 + 0] - HALF;
        int y0 = xys[s][(b * NUM_PATCHES + NUM_PATCHES - 1) * 2 + 1] - HALF;
        x0 = max(0, min(x0, HH - PP));
        y0 = max(0, min(y0, WW - PP));
        for (int i = tid; i < 3 * PP * PP; i += blockDim.x) {
            int c = i / (PP * PP);
            int r = (i / PP) % PP;
            int q = i % PP;
            out[s * BB * 3 * PP * PP + b * 3 * PP * PP + i] =
                image[(size_t)(b * 3 + c) * HWSZ + (x0 + r) * WW + (y0 + q)];
        }
    }

    // encoded_anchor_patches uses n_xy (matches reference) + BN3 + lrelu
    int nx = n_xy[(b * NUM_PATCHES + NUM_PATCHES - 1) * 2 + 0];
    int ny = n_xy[(b * NUM_PATCHES + NUM_PATCHES - 1) * 2 + 1];
    for (int c = tid; c < 128; c += blockDim.x) {
        float v = g_y3[(size_t)(b * 128 + c) * HWSZ + nx * WW + ny];
        v = fmaf(g_scale3[c], v, g_shift3[c]);
        v = v > 0.f ? v : 0.01f * v;
        out[3 * BB * 3 * PP * PP + b * 128 + c] = v;
    }
}

// ---------------- launch ----------------
extern "C" void kernel_launch(void* const* d_in, const int* in_sizes, int n_in,
                              void* d_out, int out_size)
{
    (void)in_sizes; (void)n_in; (void)out_size;
    const float* image = (const float*)d_in[0];
    const int*   a_xy  = (const int*)d_in[1];
    const int*   p_xy  = (const int*)d_in[2];
    const int*   n_xy  = (const int*)d_in[3];
    const float* w1    = (const float*)d_in[4];
    const float* b1    = (const float*)d_in[5];
    const float* g1    = (const float*)d_in[6];
    const float* bt1   = (const float*)d_in[7];
    const float* w2    = (const float*)d_in[8];
    const float* b2    = (const float*)d_in[9];
    const float* g2    = (const float*)d_in[10];
    const float* bt2   = (const float*)d_in[11];
    const float* w3    = (const float*)d_in[12];
    const float* b3    = (const float*)d_in[13];
    const float* g3    = (const float*)d_in[14];
    const float* bt3   = (const float*)d_in[15];
    // d_in[16] recon_w, d_in[17] recon_b: computed but not returned by reference
    float* out = (float*)d_out;

    dim3 blk(256);
    // layer 1: 3 -> 32
    conv3x3_kernel<1, 3, 32><<<dim3(WW/32, HH/64, BB * (32/8)), blk>>>(image, w1, b1);
    bn_partial_kernel<1, 32><<<32 * BB, 256>>>();
    bn_final_kernel<1, 32><<<1, 32>>>(g1, bt1);
    // layer 2: 32 -> 64 (BN1+lrelu fused into input load)
    conv3x3_kernel<2, 32, 64><<<dim3(WW/32, HH/64, BB * (64/8)), blk>>>(image, w2, b2);
    bn_partial_kernel<2, 64><<<64 * BB, 256>>>();
    bn_final_kernel<2, 64><<<1, 64>>>(g2, bt2);
    // layer 3: 64 -> 128 (BN2+lrelu fused)
    conv3x3_kernel<3, 64, 128><<<dim3(WW/32, HH/64, BB * (128/8)), blk>>>(image, w3, b3);
    bn_partial_kernel<3, 128><<<128 * BB, 256>>>();
    bn_final_kernel<3, 128><<<1, 128>>>(g3, bt3);
    // outputs
    finalize_kernel<<<BB, 256>>>(image, a_xy, p_xy, n_xy, out);
}

// round 16
// speedup vs baseline: 1.4239x; 1.1864x over previous
#include <cuda_runtime.h>

// Problem constants
#define BB 8
#define HH 256
#define WW 256
#define HWSZ (HH*WW)
#define PP 7
#define HALF 3
#define NUM_PATCHES 32
#define BN_EPS 1e-5f

// ---------------- scratch (device globals; no allocations) ----------------
__device__ float g_y1[BB * 32  * HWSZ];   //  64 MB
__device__ float g_y2[BB * 64  * HWSZ];   // 128 MB
__device__ float g_y3[BB * 128 * HWSZ];   // 256 MB
__device__ float g_scale1[32],  g_shift1[32];
__device__ float g_scale2[64],  g_shift2[64];
__device__ float g_scale3[128], g_shift3[128];
// per-(channel,batch,tile) partial sums; 64 tiles per image plane
__device__ float g_bsum[128 * BB * 64];
__device__ float g_bsq [128 * BB * 64];

// ---------------- packed f32x2 helpers (sm_100+ PTX) ----------------
__device__ __forceinline__ unsigned long long pk2(float lo, float hi) {
    unsigned long long r;
    asm("mov.b64 %0, {%1, %2};" : "=l"(r) : "f"(lo), "f"(hi));
    return r;
}
__device__ __forceinline__ void upk2(unsigned long long v, float& lo, float& hi) {
    asm("mov.b64 {%0, %1}, %2;" : "=f"(lo), "=f"(hi) : "l"(v));
}
__device__ __forceinline__ void ffma2(unsigned long long& c,
                                      unsigned long long a,
                                      unsigned long long b) {
    asm("fma.rn.f32x2 %0, %1, %2, %3;" : "=l"(c) : "l"(a), "l"(b), "l"(c));
}

// ---------------- conv 3x3 SAME, fused input-affine+lrelu, FFMA2 ----------
// LAYER 1: img -> g_y1 ; 2: g_y1 -> g_y2 (affine1+lrelu) ; 3: g_y2 -> g_y3 (affine2+lrelu)
// Epilogue: per-block BN partial sums -> g_bsum/g_bsq (deterministic order).
template<int LAYER, int IC, int OC>
__global__ __launch_bounds__(256, 2)
void conv3x3_kernel(const float* __restrict__ img,
                    const float* __restrict__ wgt,   // (OC, IC, 3, 3)
                    const float* __restrict__ bias)  // (OC)
{
    constexpr int OCC  = 8;                    // output channels per block
    constexpr int TW   = 32;                   // tile width
    constexpr int TH   = 32;                   // tile height (4 rows per thread)
    constexpr int SW   = TW + 2;               // 34
    constexpr int TILE = (TH + 2) * SW;        // 1156
    constexpr int NL   = (TILE + 255) / 256;   // 5 loads per thread
    constexpr bool AFFINE = (LAYER != 1);

    const float* in  = (LAYER == 1) ? img  : (LAYER == 2 ? g_y1 : g_y2);
    float*       out = (LAYER == 1) ? g_y1 : (LAYER == 2 ? g_y2 : g_y3);
    const float* scl = (LAYER == 2) ? g_scale1 : g_scale2;
    const float* shf = (LAYER == 2) ? g_shift1 : g_shift2;

    __shared__ float  s_in[2][TILE];           // double buffered input tile
    __shared__ float2 s_w2[OCC * IC * 9];      // duplicated weights for LDS.64 broadcast
    __shared__ float  r_s[OCC][8], r_s2[OCC][8];

    const int tid = threadIdx.x;
    const int tx  = tid & 31;
    const int ty  = tid >> 5;                  // 0..7
    const int x0  = blockIdx.x * TW;
    const int y0  = blockIdx.y * TH;
    const int bz  = blockIdx.z;
    const int b   = bz / (OC / OCC);
    const int oc0 = (bz % (OC / OCC)) * OCC;

    // preload + duplicate this block's weight chunk: [OCC][IC][9] as (w,w)
    for (int i = tid; i < OCC * IC * 9; i += 256) {
        int ocl = i / (IC * 9);
        int rem = i - ocl * (IC * 9);
        float w = wgt[(oc0 + ocl) * IC * 9 + rem];
        s_w2[i] = make_float2(w, w);
    }

    // ---- precompute staging geometry ONCE (kills per-ic div/mod ALU) ----
    int s_idx[NL];   // smem index or -1 (thread beyond tile)
    int g_off[NL];   // gmem offset or -1 (out of bounds -> zero pad)
    #pragma unroll
    for (int j = 0; j < NL; j++) {
        int i = j * 256 + tid;
        if (i < TILE) {
            int r  = i / SW;
            int c  = i - r * SW;
            int gy = y0 - 1 + r;
            int gx = x0 - 1 + c;
            s_idx[j] = i;
            g_off[j] = ((unsigned)gy < HH && (unsigned)gx < WW) ? (gy * WW + gx) : -1;
        } else {
            s_idx[j] = -1;
            g_off[j] = -1;
        }
    }

    unsigned long long acc[2][OCC];            // 2 row-pairs x OCC
    #pragma unroll
    for (int pp = 0; pp < 2; pp++)
        #pragma unroll
        for (int o = 0; o < OCC; o++) acc[pp][o] = 0ULL;

    const float* inb = in + (size_t)b * IC * HWSZ;

    // prefetch + stage ic = 0 into buffer 0
    float pf[NL];
    {
        const float* inc = inb;
        #pragma unroll
        for (int j = 0; j < NL; j++)
            pf[j] = (g_off[j] >= 0) ? __ldg(inc + g_off[j]) : 0.f;
        float sc = 1.f, sh = 0.f;
        if (AFFINE) { sc = scl[0]; sh = shf[0]; }
        #pragma unroll
        for (int j = 0; j < NL; j++) {
            if (s_idx[j] >= 0) {
                float v = 0.f;
                if (g_off[j] >= 0) {
                    v = pf[j];
                    if (AFFINE) { v = fmaf(sc, v, sh); v = v > 0.f ? v : 0.01f * v; }
                }
                s_in[0][s_idx[j]] = v;
            }
        }
    }
    __syncthreads();

    for (int ic = 0; ic < IC; ic++) {
        const int buf = ic & 1;

        // issue next ic's global loads now; latency hides under compute below
        if (ic + 1 < IC) {
            const float* inc = inb + (size_t)(ic + 1) * HWSZ;
            #pragma unroll
            for (int j = 0; j < NL; j++)
                pf[j] = (g_off[j] >= 0) ? __ldg(inc + g_off[j]) : 0.f;
        }

        // pack vertical row-pairs from rows ty*4 .. ty*4+5 (compile-time offsets)
        const float* sb = &s_in[buf][(ty * 4) * SW + tx];
        unsigned long long vp[5][3];
        #pragma unroll
        for (int c = 0; c < 3; c++) {
            float prev = sb[c];
            #pragma unroll
            for (int r = 0; r < 5; r++) {
                float nxt = sb[(r + 1) * SW + c];
                vp[r][c] = pk2(prev, nxt);
                prev = nxt;
            }
        }

        #pragma unroll
        for (int o = 0; o < OCC; o++) {
            const float2* wp = &s_w2[(o * IC + ic) * 9];
            unsigned long long w[9];
            #pragma unroll
            for (int k = 0; k < 9; k++)
                w[k] = *reinterpret_cast<const unsigned long long*>(&wp[k]);
            #pragma unroll
            for (int pp = 0; pp < 2; pp++)
                #pragma unroll
                for (int kr = 0; kr < 3; kr++)
                    #pragma unroll
                    for (int kc = 0; kc < 3; kc++)
                        ffma2(acc[pp][o], vp[2 * pp + kr][kc], w[kr * 3 + kc]);
        }

        // stage ic+1 into the other buffer (pf LDGs have had a full compute
        // phase to land), then single sync
        if (ic + 1 < IC) {
            float sc = 1.f, sh = 0.f;
            if (AFFINE) { sc = scl[ic + 1]; sh = shf[ic + 1]; }
            #pragma unroll
            for (int j = 0; j < NL; j++) {
                if (s_idx[j] >= 0) {
                    float v = 0.f;
                    if (g_off[j] >= 0) {
                        v = pf[j];
                        if (AFFINE) { v = fmaf(sc, v, sh); v = v > 0.f ? v : 0.01f * v; }
                    }
                    s_in[buf ^ 1][s_idx[j]] = v;
                }
            }
        }
        __syncthreads();
    }

    // ---- epilogue: write y = conv + bias, and BN partials (deterministic) ----
    const int tile = blockIdx.y * gridDim.x + blockIdx.x;   // 0..63
    #pragma unroll
    for (int o = 0; o < OCC; o++) {
        float bv = bias[oc0 + o];
        float* op = out + (size_t)(b * OC + oc0 + o) * HWSZ;
        float s = 0.f, s2 = 0.f;
        #pragma unroll
        for (int pp = 0; pp < 2; pp++) {
            float lo, hi;
            upk2(acc[pp][o], lo, hi);
            lo += bv; hi += bv;
            int gy = y0 + ty * 4 + 2 * pp;
            op[gy * WW + x0 + tx]       = lo;
            op[(gy + 1) * WW + x0 + tx] = hi;
            s += lo + hi;
            s2 = fmaf(lo, lo, s2);
            s2 = fmaf(hi, hi, s2);
        }
        // warp butterfly reduce (fixed order -> deterministic)
        #pragma unroll
        for (int m = 16; m > 0; m >>= 1) {
            s  += __shfl_xor_sync(0xFFFFFFFFu, s,  m);
            s2 += __shfl_xor_sync(0xFFFFFFFFu, s2, m);
        }
        if (tx == 0) { r_s[o][ty] = s; r_s2[o][ty] = s2; }
    }
    __syncthreads();
    if (tid < OCC) {
        float s = 0.f, s2 = 0.f;
        #pragma unroll
        for (int k = 0; k < 8; k++) { s += r_s[tid][k]; s2 += r_s2[tid][k]; }
        int slot = ((oc0 + tid) * BB + b) * 64 + tile;
        g_bsum[slot] = s;
        g_bsq[slot]  = s2;
    }
}

// ---------------- BN finalize: reduce 512 partials/channel ----------------
template<int LAYER, int C>
__global__ __launch_bounds__(512)
void bn_final_kernel(const float* __restrict__ gamma,
                     const float* __restrict__ beta)
{
    float* scale = (LAYER == 1) ? g_scale1 : (LAYER == 2 ? g_scale2 : g_scale3);
    float* shift = (LAYER == 1) ? g_shift1 : (LAYER == 2 ? g_shift2 : g_shift3);
    const int c = blockIdx.x;

    __shared__ float rs[512], rs2[512];
    rs[threadIdx.x]  = g_bsum[c * (BB * 64) + threadIdx.x];
    rs2[threadIdx.x] = g_bsq [c * (BB * 64) + threadIdx.x];
    __syncthreads();
    for (int off = 256; off > 0; off >>= 1) {
        if (threadIdx.x < off) {
            rs[threadIdx.x]  += rs[threadIdx.x + off];
            rs2[threadIdx.x] += rs2[threadIdx.x + off];
        }
        __syncthreads();
    }
    if (threadIdx.x == 0) {
        const float n = (float)(BB * HWSZ);
        float mean = rs[0] / n;
        float var  = rs2[0] / n - mean * mean;
        float sc   = gamma[c] * rsqrtf(var + BN_EPS);
        scale[c]   = sc;
        shift[c]   = beta[c] - mean * sc;
    }
}

// ---------------- patches (from raw image) + encoded gather ----------------
__global__ void finalize_kernel(const float* __restrict__ image,
                                const int* __restrict__ a_xy,
                                const int* __restrict__ p_xy,
                                const int* __restrict__ n_xy,
                                float* __restrict__ out)
{
    const int b   = blockIdx.x;
    const int tid = threadIdx.x;
    const int* xys[3] = { a_xy, p_xy, n_xy };

    #pragma unroll
    for (int s = 0; s < 3; s++) {
        int x0 = xys[s][(b * NUM_PATCHES + NUM_PATCHES - 1) * 2 + 0] - HALF;
        int y0 = xys[s][(b * NUM_PATCHES + NUM_PATCHES - 1) * 2 + 1] - HALF;
        x0 = max(0, min(x0, HH - PP));
        y0 = max(0, min(y0, WW - PP));
        for (int i = tid; i < 3 * PP * PP; i += blockDim.x) {
            int c = i / (PP * PP);
            int r = (i / PP) % PP;
            int q = i % PP;
            out[s * BB * 3 * PP * PP + b * 3 * PP * PP + i] =
                image[(size_t)(b * 3 + c) * HWSZ + (x0 + r) * WW + (y0 + q)];
        }
    }

    // encoded_anchor_patches uses n_xy (matches reference) + BN3 + lrelu
    int nx = n_xy[(b * NUM_PATCHES + NUM_PATCHES - 1) * 2 + 0];
    int ny = n_xy[(b * NUM_PATCHES + NUM_PATCHES - 1) * 2 + 1];
    for (int c = tid; c < 128; c += blockDim.x) {
        float v = g_y3[(size_t)(b * 128 + c) * HWSZ + nx * WW + ny];
        v = fmaf(g_scale3[c], v, g_shift3[c]);
        v = v > 0.f ? v : 0.01f * v;
        out[3 * BB * 3 * PP * PP + b * 128 + c] = v;
    }
}

// ---------------- launch ----------------
extern "C" void kernel_launch(void* const* d_in, const int* in_sizes, int n_in,
                              void* d_out, int out_size)
{
    (void)in_sizes; (void)n_in; (void)out_size;
    const float* image = (const float*)d_in[0];
    const int*   a_xy  = (const int*)d_in[1];
    const int*   p_xy  = (const int*)d_in[2];
    const int*   n_xy  = (const int*)d_in[3];
    const float* w1    = (const float*)d_in[4];
    const float* b1    = (const float*)d_in[5];
    const float* g1    = (const float*)d_in[6];
    const float* bt1   = (const float*)d_in[7];
    const float* w2    = (const float*)d_in[8];
    const float* b2    = (const float*)d_in[9];
    const float* g2    = (const float*)d_in[10];
    const float* bt2   = (const float*)d_in[11];
    const float* w3    = (const float*)d_in[12];
    const float* b3    = (const float*)d_in[13];
    const float* g3    = (const float*)d_in[14];
    const float* bt3   = (const float*)d_in[15];
    // d_in[16] recon_w, d_in[17] recon_b: computed but not returned by reference
    float* out = (float*)d_out;

    dim3 blk(256);
    // layer 1: 3 -> 32
    conv3x3_kernel<1, 3, 32><<<dim3(WW/32, HH/32, BB * (32/8)), blk>>>(image, w1, b1);
    bn_final_kernel<1, 32><<<32, 512>>>(g1, bt1);
    // layer 2: 32 -> 64 (BN1+lrelu fused into input load)
    conv3x3_kernel<2, 32, 64><<<dim3(WW/32, HH/32, BB * (64/8)), blk>>>(image, w2, b2);
    bn_final_kernel<2, 64><<<64, 512>>>(g2, bt2);
    // layer 3: 64 -> 128 (BN2+lrelu fused)
    conv3x3_kernel<3, 64, 128><<<dim3(WW/32, HH/32, BB * (128/8)), blk>>>(image, w3, b3);
    bn_final_kernel<3, 128><<<128, 512>>>(g3, bt3);
    // outputs
    finalize_kernel<<<BB, 256>>>(image, a_xy, p_xy, n_xy, out);
}

// round 17
// speedup vs baseline: 1.6770x; 1.1778x over previous
#include <cuda_runtime.h>

// Problem constants
#define BB 8
#define HH 256
#define WW 256
#define HWSZ (HH*WW)
#define PP 7
#define HALF 3
#define NUM_PATCHES 32
#define BN_EPS 1e-5f

// ---------------- scratch (device globals; no allocations) ----------------
__device__ float g_y1[BB * 32  * HWSZ];   //  64 MB
__device__ float g_y2[BB * 64  * HWSZ];   // 128 MB
__device__ float g_y3[BB * 128 * HWSZ];   // 256 MB
__device__ float g_scale1[32],  g_shift1[32];
__device__ float g_scale2[64],  g_shift2[64];
__device__ float g_scale3[128], g_shift3[128];
// per-(channel,batch,tile) partial sums; 64 tiles per image plane
__device__ float g_bsum[128 * BB * 64];
__device__ float g_bsq [128 * BB * 64];

// ---------------- packed f32x2 helpers (sm_100+ PTX) ----------------
__device__ __forceinline__ void upk2(unsigned long long v, float& lo, float& hi) {
    asm("mov.b64 {%0, %1}, %2;" : "=f"(lo), "=f"(hi) : "l"(v));
}
__device__ __forceinline__ void ffma2(unsigned long long& c,
                                      unsigned long long a,
                                      unsigned long long b) {
    asm("fma.rn.f32x2 %0, %1, %2, %3;" : "=l"(c) : "l"(a), "l"(b), "l"(c));
}

// ---------------- conv 3x3 SAME, fused input-affine+lrelu, FFMA2 ----------
// f32x2 lanes carry ADJACENT OUTPUT CHANNELS (oc-pairs):
//   - weights pre-packed (w[2o], w[2o+1]) in smem, 4 pairs contiguous -> LDS.128
//   - inputs duplicated (v,v) at staging time -> vin is plain LDS.64, no movs
// LAYER 1: img -> g_y1 ; 2: g_y1 -> g_y2 (affine1+lrelu) ; 3: g_y2 -> g_y3 (affine2+lrelu)
// Epilogue: per-block BN partial sums -> g_bsum/g_bsq (deterministic order).
template<int LAYER, int IC, int OC>
__global__ __launch_bounds__(256, 2)
void conv3x3_kernel(const float* __restrict__ img,
                    const float* __restrict__ wgt,   // (OC, IC, 3, 3)
                    const float* __restrict__ bias)  // (OC)
{
    constexpr int OCC  = 8;                    // output channels per block (4 pairs)
    constexpr int TW   = 32;                   // tile width
    constexpr int TH   = 32;                   // tile height (4 rows per thread)
    constexpr int SW   = TW + 2;               // 34
    constexpr int TILE = (TH + 2) * SW;        // 1156
    constexpr int NL   = (TILE + 255) / 256;   // 5 loads per thread
    constexpr bool AFFINE = (LAYER != 1);

    const float* in  = (LAYER == 1) ? img  : (LAYER == 2 ? g_y1 : g_y2);
    float*       out = (LAYER == 1) ? g_y1 : (LAYER == 2 ? g_y2 : g_y3);
    const float* scl = (LAYER == 2) ? g_scale1 : g_scale2;
    const float* shf = (LAYER == 2) ? g_shift1 : g_shift2;

    __shared__ float2 s_in[2][TILE];                     // (v,v) duplicated input
    alignas(16) __shared__ float2 s_w2[IC * 9 * 4];      // [(ic*9+tap)*4 + ocp] = (w2o, w2o+1)
    __shared__ float  r_s[OCC][8], r_s2[OCC][8];

    const int tid = threadIdx.x;
    const int tx  = tid & 31;
    const int ty  = tid >> 5;                  // 0..7
    const int x0  = blockIdx.x * TW;
    const int y0  = blockIdx.y * TH;
    const int bz  = blockIdx.z;
    const int b   = bz / (OC / OCC);
    const int oc0 = (bz % (OC / OCC)) * OCC;

    // pack this block's weight chunk into oc-pairs: [(ic*9+tap)*4 + ocp]
    for (int i = tid; i < IC * 9 * 4; i += 256) {
        int ocp = i & 3;
        int tap = (i >> 2) % 9;
        int ic  = i / 36;
        float wlo = wgt[(oc0 + 2 * ocp)     * IC * 9 + ic * 9 + tap];
        float whi = wgt[(oc0 + 2 * ocp + 1) * IC * 9 + ic * 9 + tap];
        s_w2[i] = make_float2(wlo, whi);
    }

    // ---- precompute staging geometry ONCE ----
    int s_idx[NL];   // smem index or -1
    int g_off[NL];   // gmem offset or -1 (zero pad)
    #pragma unroll
    for (int j = 0; j < NL; j++) {
        int i = j * 256 + tid;
        if (i < TILE) {
            int r  = i / SW;
            int c  = i - r * SW;
            int gy = y0 - 1 + r;
            int gx = x0 - 1 + c;
            s_idx[j] = i;
            g_off[j] = ((unsigned)gy < HH && (unsigned)gx < WW) ? (gy * WW + gx) : -1;
        } else {
            s_idx[j] = -1;
            g_off[j] = -1;
        }
    }

    unsigned long long acc[4][4];              // [row][oc-pair]
    #pragma unroll
    for (int r = 0; r < 4; r++)
        #pragma unroll
        for (int p = 0; p < 4; p++) acc[r][p] = 0ULL;

    const float* inb = in + (size_t)b * IC * HWSZ;

    // prefetch + stage ic = 0 into buffer 0
    float pf[NL];
    {
        const float* inc = inb;
        #pragma unroll
        for (int j = 0; j < NL; j++)
            pf[j] = (g_off[j] >= 0) ? __ldg(inc + g_off[j]) : 0.f;
        float sc = 1.f, sh = 0.f;
        if (AFFINE) { sc = scl[0]; sh = shf[0]; }
        #pragma unroll
        for (int j = 0; j < NL; j++) {
            if (s_idx[j] >= 0) {
                float v = 0.f;
                if (g_off[j] >= 0) {
                    v = pf[j];
                    if (AFFINE) { v = fmaf(sc, v, sh); v = v > 0.f ? v : 0.01f * v; }
                }
                s_in[0][s_idx[j]] = make_float2(v, v);
            }
        }
    }
    __syncthreads();

    for (int ic = 0; ic < IC; ic++) {
        const int buf = ic & 1;

        // issue next ic's global loads now; latency hides under compute below
        if (ic + 1 < IC) {
            const float* inc = inb + (size_t)(ic + 1) * HWSZ;
            #pragma unroll
            for (int j = 0; j < NL; j++)
                pf[j] = (g_off[j] >= 0) ? __ldg(inc + g_off[j]) : 0.f;
        }

        // load 6 halo rows x 3 cols of duplicated input (LDS.64 each)
        const unsigned long long* sb =
            reinterpret_cast<const unsigned long long*>(&s_in[buf][(ty * 4) * SW + tx]);
        unsigned long long vv[6][3];
        #pragma unroll
        for (int r = 0; r < 6; r++)
            #pragma unroll
            for (int c = 0; c < 3; c++)
                vv[r][c] = sb[r * SW + c];

        // 9 taps: each = 2x LDS.128 (4 weight pairs) + 16 FFMA2
        const ulonglong2* wp =
            reinterpret_cast<const ulonglong2*>(&s_w2[ic * 36]);
        #pragma unroll
        for (int kr = 0; kr < 3; kr++) {
            #pragma unroll
            for (int kc = 0; kc < 3; kc++) {
                const int tap = kr * 3 + kc;
                ulonglong2 wa = wp[tap * 2];
                ulonglong2 wb = wp[tap * 2 + 1];
                #pragma unroll
                for (int r = 0; r < 4; r++) {
                    ffma2(acc[r][0], vv[r + kr][kc], wa.x);
                    ffma2(acc[r][1], vv[r + kr][kc], wa.y);
                    ffma2(acc[r][2], vv[r + kr][kc], wb.x);
                    ffma2(acc[r][3], vv[r + kr][kc], wb.y);
                }
            }
        }

        // stage ic+1 into the other buffer, then single sync
        if (ic + 1 < IC) {
            float sc = 1.f, sh = 0.f;
            if (AFFINE) { sc = scl[ic + 1]; sh = shf[ic + 1]; }
            #pragma unroll
            for (int j = 0; j < NL; j++) {
                if (s_idx[j] >= 0) {
                    float v = 0.f;
                    if (g_off[j] >= 0) {
                        v = pf[j];
                        if (AFFINE) { v = fmaf(sc, v, sh); v = v > 0.f ? v : 0.01f * v; }
                    }
                    s_in[buf ^ 1][s_idx[j]] = make_float2(v, v);
                }
            }
        }
        __syncthreads();
    }

    // ---- epilogue: write y = conv + bias, and BN partials (deterministic) ----
    const int tile = blockIdx.y * gridDim.x + blockIdx.x;   // 0..63
    #pragma unroll
    for (int ocp = 0; ocp < 4; ocp++) {
        float blo = bias[oc0 + 2 * ocp];
        float bhi = bias[oc0 + 2 * ocp + 1];
        float* oplo = out + (size_t)(b * OC + oc0 + 2 * ocp) * HWSZ;
        float* ophi = oplo + HWSZ;
        float slo = 0.f, s2lo = 0.f, shi = 0.f, s2hi = 0.f;
        #pragma unroll
        for (int r = 0; r < 4; r++) {
            float lo, hi;
            upk2(acc[r][ocp], lo, hi);
            lo += blo; hi += bhi;
            int gy = y0 + ty * 4 + r;
            oplo[gy * WW + x0 + tx] = lo;
            ophi[gy * WW + x0 + tx] = hi;
            slo += lo; s2lo = fmaf(lo, lo, s2lo);
            shi += hi; s2hi = fmaf(hi, hi, s2hi);
        }
        #pragma unroll
        for (int m = 16; m > 0; m >>= 1) {
            slo  += __shfl_xor_sync(0xFFFFFFFFu, slo,  m);
            s2lo += __shfl_xor_sync(0xFFFFFFFFu, s2lo, m);
            shi  += __shfl_xor_sync(0xFFFFFFFFu, shi,  m);
            s2hi += __shfl_xor_sync(0xFFFFFFFFu, s2hi, m);
        }
        if (tx == 0) {
            r_s[2 * ocp][ty]     = slo;  r_s2[2 * ocp][ty]     = s2lo;
            r_s[2 * ocp + 1][ty] = shi;  r_s2[2 * ocp + 1][ty] = s2hi;
        }
    }
    __syncthreads();
    if (tid < OCC) {
        float s = 0.f, s2 = 0.f;
        #pragma unroll
        for (int k = 0; k < 8; k++) { s += r_s[tid][k]; s2 += r_s2[tid][k]; }
        int slot = ((oc0 + tid) * BB + b) * 64 + tile;
        g_bsum[slot] = s;
        g_bsq[slot]  = s2;
    }
}

// ---------------- BN finalize: reduce 512 partials/channel ----------------
template<int LAYER, int C>
__global__ __launch_bounds__(512)
void bn_final_kernel(const float* __restrict__ gamma,
                     const float* __restrict__ beta)
{
    float* scale = (LAYER == 1) ? g_scale1 : (LAYER == 2 ? g_scale2 : g_scale3);
    float* shift = (LAYER == 1) ? g_shift1 : (LAYER == 2 ? g_shift2 : g_shift3);
    const int c = blockIdx.x;

    __shared__ float rs[512], rs2[512];
    rs[threadIdx.x]  = g_bsum[c * (BB * 64) + threadIdx.x];
    rs2[threadIdx.x] = g_bsq [c * (BB * 64) + threadIdx.x];
    __syncthreads();
    for (int off = 256; off > 0; off >>= 1) {
        if (threadIdx.x < off) {
            rs[threadIdx.x]  += rs[threadIdx.x + off];
            rs2[threadIdx.x] += rs2[threadIdx.x + off];
        }
        __syncthreads();
    }
    if (threadIdx.x == 0) {
        const float n = (float)(BB * HWSZ);
        float mean = rs[0] / n;
        float var  = rs2[0] / n - mean * mean;
        float sc   = gamma[c] * rsqrtf(var + BN_EPS);
        scale[c]   = sc;
        shift[c]   = beta[c] - mean * sc;
    }
}

// ---------------- patches (from raw image) + encoded gather ----------------
__global__ void finalize_kernel(const float* __restrict__ image,
                                const int* __restrict__ a_xy,
                                const int* __restrict__ p_xy,
                                const int* __restrict__ n_xy,
                                float* __restrict__ out)
{
    const int b   = blockIdx.x;
    const int tid = threadIdx.x;
    const int* xys[3] = { a_xy, p_xy, n_xy };

    #pragma unroll
    for (int s = 0; s < 3; s++) {
        int x0 = xys[s][(b * NUM_PATCHES + NUM_PATCHES - 1) * 2 + 0] - HALF;
        int y0 = xys[s][(b * NUM_PATCHES + NUM_PATCHES - 1) * 2 + 1] - HALF;
        x0 = max(0, min(x0, HH - PP));
        y0 = max(0, min(y0, WW - PP));
        for (int i = tid; i < 3 * PP * PP; i += blockDim.x) {
            int c = i / (PP * PP);
            int r = (i / PP) % PP;
            int q = i % PP;
            out[s * BB * 3 * PP * PP + b * 3 * PP * PP + i] =
                image[(size_t)(b * 3 + c) * HWSZ + (x0 + r) * WW + (y0 + q)];
        }
    }

    // encoded_anchor_patches uses n_xy (matches reference) + BN3 + lrelu
    int nx = n_xy[(b * NUM_PATCHES + NUM_PATCHES - 1) * 2 + 0];
    int ny = n_xy[(b * NUM_PATCHES + NUM_PATCHES - 1) * 2 + 1];
    for (int c = tid; c < 128; c += blockDim.x) {
        float v = g_y3[(size_t)(b * 128 + c) * HWSZ + nx * WW + ny];
        v = fmaf(g_scale3[c], v, g_shift3[c]);
        v = v > 0.f ? v : 0.01f * v;
        out[3 * BB * 3 * PP * PP + b * 128 + c] = v;
    }
}

// ---------------- launch ----------------
extern "C" void kernel_launch(void* const* d_in, const int* in_sizes, int n_in,
                              void* d_out, int out_size)
{
    (void)in_sizes; (void)n_in; (void)out_size;
    const float* image = (const float*)d_in[0];
    const int*   a_xy  = (const int*)d_in[1];
    const int*   p_xy  = (const int*)d_in[2];
    const int*   n_xy  = (const int*)d_in[3];
    const float* w1    = (const float*)d_in[4];
    const float* b1    = (const float*)d_in[5];
    const float* g1    = (const float*)d_in[6];
    const float* bt1   = (const float*)d_in[7];
    const float* w2    = (const float*)d_in[8];
    const float* b2    = (const float*)d_in[9];
    const float* g2    = (const float*)d_in[10];
    const float* bt2   = (const float*)d_in[11];
    const float* w3    = (const float*)d_in[12];
    const float* b3    = (const float*)d_in[13];
    const float* g3    = (const float*)d_in[14];
    const float* bt3   = (const float*)d_in[15];
    // d_in[16] recon_w, d_in[17] recon_b: computed but not returned by reference
    float* out = (float*)d_out;

    dim3 blk(256);
    // layer 1: 3 -> 32
    conv3x3_kernel<1, 3, 32><<<dim3(WW/32, HH/32, BB * (32/8)), blk>>>(image, w1, b1);
    bn_final_kernel<1, 32><<<32, 512>>>(g1, bt1);
    // layer 2: 32 -> 64 (BN1+lrelu fused into input load)
    conv3x3_kernel<2, 32, 64><<<dim3(WW/32, HH/32, BB * (64/8)), blk>>>(image, w2, b2);
    bn_final_kernel<2, 64><<<64, 512>>>(g2, bt2);
    // layer 3: 64 -> 128 (BN2+lrelu fused)
    conv3x3_kernel<3, 64, 128><<<dim3(WW/32, HH/32, BB * (128/8)), blk>>>(image, w3, b3);
    bn_final_kernel<3, 128><<<128, 512>>>(g3, bt3);
    // outputs
    finalize_kernel<<<BB, 256>>>(image, a_xy, p_xy, n_xy, out);
}